// round 5
// baseline (speedup 1.0000x reference)
#include <cuda_runtime.h>
#include <cstdint>

#define MODES 16
#define LOG2E 1.4426950408889634f
#define LN2   0.6931471805599453f
#define E_CONST 2.7182818284590452f
#define TAU   0.25f   /* 1/sqrt(16) */

#define VMIN_BLOCKS 1184   /* 16 * 74 */

typedef unsigned long long u64;

// Scratch: per-block partial minima (plain stores, needs no init) + ticket.
__device__ float    g_part[VMIN_BLOCKS][MODES];
__device__ float    g_vmin[MODES];
__device__ unsigned g_ticket;   // static-init 0; last block resets to 0 -> replay-safe

__device__ __forceinline__ float ex2_approx(float x) {
    float r; asm("ex2.approx.f32 %0, %1;" : "=f"(r) : "f"(x)); return r;
}
__device__ __forceinline__ float rcp_approx(float x) {
    float r; asm("rcp.approx.f32 %0, %1;" : "=f"(r) : "f"(x)); return r;
}

// ---- packed f32x2 helpers ----
__device__ __forceinline__ u64 pk2(float lo, float hi) {
    u64 r; asm("mov.b64 %0, {%1, %2};" : "=l"(r) : "f"(lo), "f"(hi)); return r;
}
__device__ __forceinline__ void up2(u64 v, float& lo, float& hi) {
    asm("mov.b64 {%0, %1}, %2;" : "=f"(lo), "=f"(hi) : "l"(v));
}
__device__ __forceinline__ u64 add2(u64 a, u64 b) {
    u64 r; asm("add.rn.f32x2 %0, %1, %2;" : "=l"(r) : "l"(a), "l"(b)); return r;
}
__device__ __forceinline__ u64 mul2(u64 a, u64 b) {
    u64 r; asm("mul.rn.f32x2 %0, %1, %2;" : "=l"(r) : "l"(a), "l"(b)); return r;
}
__device__ __forceinline__ u64 fma2(u64 a, u64 b, u64 c) {
    u64 r; asm("fma.rn.f32x2 %0, %1, %2, %3;" : "=l"(r) : "l"(a), "l"(b), "l"(c)); return r;
}
// Duplicate a compile-time float into both halves (no hand-encoded hex).
__device__ __forceinline__ u64 dupf(float v) {
    unsigned u = __float_as_uint(v);
    return (((u64)u) << 32) | (u64)u;
}

// Audited hex-duplicated poly coefficients (Taylor of 2^x: c_n = ln2^n / n!).
#define DUP(x) ((((u64)(x)) << 32) | (u64)(x))
#define NEG1P DUP(0xBF800000u)  /* -1.0        */
#define ONE2  DUP(0x3F800000u)  /*  1.0        */
#define C1P   DUP(0x3F317218u)  /* 0.69314718  */
#define C2P   DUP(0x3E75FDF0u)  /* 0.24022651  */
#define C3P   DUP(0x3D635770u)  /* 0.055504109 */
#define C4P   DUP(0x3C1D962Cu)  /* 0.009618129 */
#define C5P   DUP(0x3AAEC8D8u)  /* 1.3333558e-3*/
#define C6P   DUP(0x39218400u)  /* 1.5403516e-4*/

// Per-column min over V[N, 16] with last-block final reduce (no init kernel).
__global__ void __launch_bounds__(256) comp_vmin_kernel(const float* __restrict__ V, int N) {
    float m[MODES];
#pragma unroll
    for (int j = 0; j < MODES; j++) m[j] = 3.4028235e38f;

    int stride = gridDim.x * blockDim.x;
    for (int r = blockIdx.x * blockDim.x + threadIdx.x; r < N; r += stride) {
        const float4* p = (const float4*)(V + (size_t)r * MODES);
#pragma unroll
        for (int q = 0; q < 4; q++) {
            float4 v = p[q];
            m[4 * q + 0] = fminf(m[4 * q + 0], v.x);
            m[4 * q + 1] = fminf(m[4 * q + 1], v.y);
            m[4 * q + 2] = fminf(m[4 * q + 2], v.z);
            m[4 * q + 3] = fminf(m[4 * q + 3], v.w);
        }
    }
#pragma unroll
    for (int off = 16; off; off >>= 1) {
#pragma unroll
        for (int j = 0; j < MODES; j++)
            m[j] = fminf(m[j], __shfl_xor_sync(0xFFFFFFFFu, m[j], off));
    }
    __shared__ float sred[8][MODES];
    int warp = threadIdx.x >> 5, lane = threadIdx.x & 31;
    if (lane == 0) {
#pragma unroll
        for (int j = 0; j < MODES; j++) sred[warp][j] = m[j];
    }
    __syncthreads();
    if (threadIdx.x < MODES) {
        float mm = sred[0][threadIdx.x];
#pragma unroll
        for (int wq = 1; wq < 8; wq++) mm = fminf(mm, sred[wq][threadIdx.x]);
        g_part[blockIdx.x][threadIdx.x] = mm;
    }
    __threadfence();
    __shared__ bool is_last;
    __syncthreads();
    if (threadIdx.x == 0)
        is_last = (atomicAdd(&g_ticket, 1u) == gridDim.x - 1);
    __syncthreads();
    if (is_last) {
        // 256 threads = 16 slices x 16 modes: fully parallel final reduce.
        int md = threadIdx.x & 15;
        int slice = threadIdx.x >> 4;
        float mm = 3.4028235e38f;
        const int per = VMIN_BLOCKS / 16;   // 74
        for (int bq = slice * per; bq < (slice + 1) * per; bq++)
            mm = fminf(mm, g_part[bq][md]);
        __shared__ float red2[16][17];
        red2[slice][md] = mm;
        __syncthreads();
        if (threadIdx.x < MODES) {
            float z = red2[0][threadIdx.x];
#pragma unroll
            for (int s = 1; s < 16; s++) z = fminf(z, red2[s][threadIdx.x]);
            g_vmin[threadIdx.x] = z;
        }
        if (threadIdx.x == 0) g_ticket = 0;
    }
}

// Two rows per thread, every fp op packed f32x2 across the row pair.
// P_ij = S*2^{h*d}, P_ji = S*2^{-h*d} with S = sq_i*sq_j, d = L_i-L_j, h = g-0.5.
// Far pairs (j-i>=9): even/odd deg-6 poly gives both 2^{x} and 2^{-x} on the fp
// pipe (|x| <= ~0.6). Near pairs: MUFU ex2.
__global__ void __launch_bounds__(128) comp_main_kernel(
    const float* __restrict__ V,
    const float* __restrict__ w,
    const float* __restrict__ b,
    const float* __restrict__ gammas,
    float* __restrict__ out, int N)
{
    __shared__ u64 hdup[MODES][MODES];     // (h, h) duplicated
    __shared__ float cofs[MODES], s_w[MODES], s_b[MODES];
    int t = threadIdx.x;
#pragma unroll
    for (int rep = 0; rep < 2; rep++) {
        int e = t + rep * 128;
        int i = e >> 4, j = e & 15;
        float g = (j > i) ? gammas[i * MODES + j]
                          : ((j < i) ? gammas[j * MODES + i] : 0.5f);
        float h = g - 0.5f;
        hdup[i][j] = pk2(h, h);
    }
    if (t < MODES) {
        cofs[t] = E_CONST - g_vmin[t];
        s_w[t] = 1.0f + w[t];
        s_b[t] = b[t];
    }
    __syncthreads();

    int base = blockIdx.x * 256;
    int r0 = base + t;
    int r1 = r0 + 128;
    bool ok0 = r0 < N, ok1 = r1 < N;
    int c0 = ok0 ? r0 : N - 1;
    int c1 = ok1 ? r1 : N - 1;

    const float4* p0 = (const float4*)(V + (size_t)c0 * MODES);
    const float4* p1 = (const float4*)(V + (size_t)c1 * MODES);

    u64 L2[MODES], sq2[MODES], acc2[MODES];
#pragma unroll
    for (int q = 0; q < 4; q++) {
        float4 va = p0[q], vb = p1[q];
        float aa[4] = {va.x, va.y, va.z, va.w};
        float bb[4] = {vb.x, vb.y, vb.z, vb.w};
#pragma unroll
        for (int k = 0; k < 4; k++) {
            int m = 4 * q + k;
            float x0 = fmaxf(aa[k] + cofs[m], E_CONST);
            float x1 = fmaxf(bb[k] + cofs[m], E_CONST);
            float ph0 = fmaf(s_w[m], x0, s_b[m]);
            float ph1 = fmaf(s_w[m], x1, s_b[m]);
            float l0 = __log2f(ph0), l1 = __log2f(ph1);
            float q0 = ex2_approx(0.5f * l0), q1 = ex2_approx(0.5f * l1);
            L2[m]   = pk2(l0, l1);
            sq2[m]  = pk2(q0, q1);
            acc2[m] = pk2(ph0, ph1);   // diagonal term seeds the sum
        }
    }

#pragma unroll
    for (int i = 0; i < MODES; i++) {
        u64 racc = 0;                  // (0.0f, 0.0f)
#pragma unroll
        for (int j = i + 1; j < MODES; j++) {
            u64 h2 = hdup[i][j];
            u64 d2 = fma2(L2[j], NEG1P, L2[i]);    // L_i - L_j
            u64 x2 = mul2(h2, d2);
            u64 s2 = mul2(sq2[i], sq2[j]);
            u64 u2, v2;
            if (j - i >= 9) {                      // compile-time: poly both dirs
                u64 t2 = mul2(x2, x2);
                u64 Ev = fma2(t2, C6P, C4P);
                Ev = fma2(t2, Ev, C2P);
                Ev = fma2(t2, Ev, ONE2);
                u64 Od = fma2(t2, C5P, C3P);
                Od = fma2(t2, Od, C1P);
                Od = mul2(x2, Od);
                u2 = add2(Ev, Od);                 // 2^{x}
                v2 = fma2(Od, NEG1P, Ev);          // 2^{-x}
            } else {                               // MUFU path
                u64 nx2 = mul2(x2, NEG1P);
                float xa, xb, na, nb;
                up2(x2, xa, xb);
                up2(nx2, na, nb);
                u2 = pk2(ex2_approx(xa), ex2_approx(xb));
                v2 = pk2(ex2_approx(na), ex2_approx(nb));
            }
            acc2[j] = fma2(s2, v2, acc2[j]);       // P_ji into mode j
            racc    = fma2(s2, u2, racc);          // P_ij into mode i (accum)
        }
        if (i < MODES - 1) acc2[i] = add2(acc2[i], racc);
    }

    // log_softmax of x = -tau*acc, both rows packed.
    float a0[MODES], a1[MODES];
#pragma unroll
    for (int m = 0; m < MODES; m++) up2(acc2[m], a0[m], a1[m]);
    float amin0 = a0[0], amin1 = a1[0];
#pragma unroll
    for (int m = 1; m < MODES; m++) {
        amin0 = fminf(amin0, a0[m]);
        amin1 = fminf(amin1, a1[m]);
    }

    const float nts = -TAU * LOG2E;                // -0.36067376
    u64 NTS2 = dupf(nts);                          // built from the float, not hex
    u64 nz2 = pk2(-amin0 * nts, -amin1 * nts);
    u64 sum2 = 0;
    u64 xs2[MODES], expk[MODES];
#pragma unroll
    for (int m = 0; m < MODES; m++) {
        u64 xm2 = fma2(acc2[m], NTS2, nz2);        // (acc-amin)*nts, log2-domain
        xs2[m] = xm2;
        float xa, xb;
        up2(xm2, xa, xb);
        u64 e2 = pk2(ex2_approx(xa), ex2_approx(xb));
        expk[m] = e2;
        sum2 = add2(sum2, e2);
    }
    float s0, s1;
    up2(sum2, s0, s1);
    u64 inv2 = pk2(rcp_approx(s0), rcp_approx(s1));
    u64 nls2 = pk2(-__log2f(s0), -__log2f(s1));
    u64 LN2P = dupf(LN2);

    float av0[MODES], av1[MODES], lv0[MODES], lv1[MODES];
#pragma unroll
    for (int m = 0; m < MODES; m++) {
        u64 al2 = mul2(expk[m], inv2);
        u64 lg2v = mul2(add2(xs2[m], nls2), LN2P);
        up2(al2, av0[m], av1[m]);
        up2(lg2v, lv0[m], lv1[m]);
    }

    if (ok0) {
        float* ao = out + (size_t)r0 * MODES;
        float* lo = out + (size_t)N * MODES + (size_t)r0 * MODES;
#pragma unroll
        for (int q = 0; q < 4; q++) {
            ((float4*)ao)[q] = make_float4(av0[4*q], av0[4*q+1], av0[4*q+2], av0[4*q+3]);
            ((float4*)lo)[q] = make_float4(lv0[4*q], lv0[4*q+1], lv0[4*q+2], lv0[4*q+3]);
        }
    }
    if (ok1) {
        float* ao = out + (size_t)r1 * MODES;
        float* lo = out + (size_t)N * MODES + (size_t)r1 * MODES;
#pragma unroll
        for (int q = 0; q < 4; q++) {
            ((float4*)ao)[q] = make_float4(av1[4*q], av1[4*q+1], av1[4*q+2], av1[4*q+3]);
            ((float4*)lo)[q] = make_float4(lv1[4*q], lv1[4*q+1], lv1[4*q+2], lv1[4*q+3]);
        }
    }
}

extern "C" void kernel_launch(void* const* d_in, const int* in_sizes, int n_in,
                              void* d_out, int out_size) {
    const float* V      = (const float*)d_in[0];
    const float* w      = (const float*)d_in[1];
    const float* b      = (const float*)d_in[2];
    const float* gammas = (const float*)d_in[3];
    float* out = (float*)d_out;
    int N = in_sizes[0] / MODES;

    comp_vmin_kernel<<<VMIN_BLOCKS, 256>>>(V, N);
    int blocks = (N + 255) / 256;
    comp_main_kernel<<<blocks, 128>>>(V, w, b, gammas, out, N);
}

// round 6
// speedup vs baseline: 1.1657x; 1.1657x over previous
#include <cuda_runtime.h>
#include <cstdint>

#define MODES 16
#define LOG2E 1.4426950408889634f
#define LN2   0.6931471805599453f
#define E_CONST 2.7182818284590452f
#define TAU   0.25f   /* 1/sqrt(16) */

#define VMIN_BLOCKS 592   /* 4 * 148 */

// Scratch: per-block partial minima (plain stores, needs no init) + ticket.
__device__ float    g_part[VMIN_BLOCKS][MODES];
__device__ float    g_vmin[MODES];
__device__ unsigned g_ticket;   // static-init 0; last block resets to 0 -> replay-safe

__device__ __forceinline__ float ex2_approx(float x) {
    float r; asm("ex2.approx.f32 %0, %1;" : "=f"(r) : "f"(x)); return r;
}
__device__ __forceinline__ float rcp_approx(float x) {
    float r; asm("rcp.approx.f32 %0, %1;" : "=f"(r) : "f"(x)); return r;
}

// Taylor coeffs of 2^x: c_n = ln2^n / n!  (audited decimal values)
#define C1T 0.6931471805599453f
#define C2T 0.2402265069591007f
#define C3T 0.0555041086648216f
#define C4T 0.0096181291076285f
#define C5T 0.0013333558146428f
#define C6T 0.0001540353039338f

// Per-column min over V[N, 16] with last-block final reduce (no init kernel).
__global__ void __launch_bounds__(256) comp_vmin_kernel(const float* __restrict__ V, int N) {
    float m[MODES];
#pragma unroll
    for (int j = 0; j < MODES; j++) m[j] = 3.4028235e38f;

    int stride = gridDim.x * blockDim.x;
    for (int r = blockIdx.x * blockDim.x + threadIdx.x; r < N; r += stride) {
        const float4* p = (const float4*)(V + (size_t)r * MODES);
#pragma unroll
        for (int q = 0; q < 4; q++) {
            float4 v = p[q];
            m[4 * q + 0] = fminf(m[4 * q + 0], v.x);
            m[4 * q + 1] = fminf(m[4 * q + 1], v.y);
            m[4 * q + 2] = fminf(m[4 * q + 2], v.z);
            m[4 * q + 3] = fminf(m[4 * q + 3], v.w);
        }
    }
#pragma unroll
    for (int off = 16; off; off >>= 1) {
#pragma unroll
        for (int j = 0; j < MODES; j++)
            m[j] = fminf(m[j], __shfl_xor_sync(0xFFFFFFFFu, m[j], off));
    }
    __shared__ float sred[8][MODES];
    int warp = threadIdx.x >> 5, lane = threadIdx.x & 31;
    if (lane == 0) {
#pragma unroll
        for (int j = 0; j < MODES; j++) sred[warp][j] = m[j];
    }
    __syncthreads();
    if (threadIdx.x < MODES) {
        float mm = sred[0][threadIdx.x];
#pragma unroll
        for (int wq = 1; wq < 8; wq++) mm = fminf(mm, sred[wq][threadIdx.x]);
        g_part[blockIdx.x][threadIdx.x] = mm;
    }
    __threadfence();
    __shared__ bool is_last;
    __syncthreads();
    if (threadIdx.x == 0)
        is_last = (atomicAdd(&g_ticket, 1u) == gridDim.x - 1);
    __syncthreads();
    if (is_last) {
        // 256 threads = 16 slices x 16 modes: fully parallel final reduce.
        int md = threadIdx.x & 15;
        int slice = threadIdx.x >> 4;
        float mm = 3.4028235e38f;
        const int per = VMIN_BLOCKS / 16;   // 37
        for (int bq = slice * per; bq < (slice + 1) * per; bq++)
            mm = fminf(mm, g_part[bq][md]);
        __shared__ float red2[16][17];
        red2[slice][md] = mm;
        __syncthreads();
        if (threadIdx.x < MODES) {
            float z = red2[0][threadIdx.x];
#pragma unroll
            for (int s = 1; s < 16; s++) z = fminf(z, red2[s][threadIdx.x]);
            g_vmin[threadIdx.x] = z;
        }
        if (threadIdx.x == 0) g_ticket = 0;
    }
}

// One row per thread, scalar. Symmetric split: P_ij = S*2^{x}, P_ji = S*2^{-x}
// with S = sqrt(phi_i*phi_j), x = h*d, h = g-0.5, d = L_i-L_j (|x| <= ~0.6).
// Far pairs (j-i >= 10): even/odd deg-6 Taylor gives BOTH 2^x and 2^-x on the
// fma pipe (zero MUFU). Near pairs: two MUFU ex2. Split tuned so fma ~ MUFU.
__global__ void __launch_bounds__(256) comp_main_kernel(
    const float* __restrict__ V,
    const float* __restrict__ w,
    const float* __restrict__ b,
    const float* __restrict__ gammas,
    float* __restrict__ out, int N)
{
    __shared__ float Hs[MODES][MODES];     // h = g - 0.5, symmetrized
    __shared__ float cofs[MODES], s_w[MODES], s_b[MODES];
    int t = threadIdx.x;
    if (t < MODES * MODES) {
        int i = t >> 4, j = t & 15;
        float g = (j > i) ? gammas[i * MODES + j]
                          : ((j < i) ? gammas[j * MODES + i] : 0.5f);
        Hs[i][j] = g - 0.5f;
    }
    if (t < MODES) {
        cofs[t] = E_CONST - g_vmin[t];
        s_w[t] = 1.0f + w[t];
        s_b[t] = b[t];
    }
    __syncthreads();

    int r = blockIdx.x * blockDim.x + t;
    if (r >= N) return;

    float acc[MODES], L[MODES], sq[MODES];
    {
        const float4* p = (const float4*)(V + (size_t)r * MODES);
#pragma unroll
        for (int q = 0; q < 4; q++) {
            float4 v = p[q];
            float vv[4] = {v.x, v.y, v.z, v.w};
#pragma unroll
            for (int k = 0; k < 4; k++) {
                int m = 4 * q + k;
                float vc = fmaxf(vv[k] + cofs[m], E_CONST);
                float ph = fmaf(s_w[m], vc, s_b[m]);
                acc[m] = ph;                     // diagonal seeds the sum
                float l = __log2f(ph);
                L[m] = l;
                sq[m] = ex2_approx(0.5f * l);    // sqrt(phi)
            }
        }
    }

    // acc_i += S*2^{x};  acc_j += S*2^{-x}
#pragma unroll
    for (int i = 0; i < MODES; i++) {
#pragma unroll
        for (int j = i + 1; j < MODES; j++) {
            float h = Hs[i][j];
            float d = L[i] - L[j];
            float x = h * d;
            float S = sq[i] * sq[j];
            float u, v;
            if (j - i >= 10) {                   // compile-time: poly both dirs
                float t2 = x * x;
                float Ev = fmaf(t2, C6T, C4T);
                Ev = fmaf(t2, Ev, C2T);
                Ev = fmaf(t2, Ev, 1.0f);
                float Od = fmaf(t2, C5T, C3T);
                Od = fmaf(t2, Od, C1T);
                Od = Od * x;
                u = Ev + Od;                     // 2^{x}
                v = Ev - Od;                     // 2^{-x}
            } else {                             // MUFU path
                u = ex2_approx(x);
                v = ex2_approx(-x);
            }
            acc[i] = fmaf(S, u, acc[i]);
            acc[j] = fmaf(S, v, acc[j]);
        }
    }

    // log_softmax of x = -tau*acc: x_i - xmax = -tau*(acc_i - amin)
    float t0 = fminf(acc[0], acc[1]),  t1 = fminf(acc[2], acc[3]);
    float t2m = fminf(acc[4], acc[5]), t3 = fminf(acc[6], acc[7]);
    float t4 = fminf(acc[8], acc[9]),  t5 = fminf(acc[10], acc[11]);
    float t6 = fminf(acc[12], acc[13]), t7 = fminf(acc[14], acc[15]);
    t0 = fminf(t0, t1); t2m = fminf(t2m, t3); t4 = fminf(t4, t5); t6 = fminf(t6, t7);
    float amin = fminf(fminf(t0, t2m), fminf(t4, t6));

    const float nts = -TAU * LOG2E;
    float ex[MODES];
    float s = 0.0f;
#pragma unroll
    for (int i = 0; i < MODES; i++) {
        float e2v = ex2_approx((acc[i] - amin) * nts);
        ex[i] = e2v;
        s += e2v;
    }
    float lns = __log2f(s) * LN2;
    float inv_s = rcp_approx(s);

    float* alpha_out = out + (size_t)r * MODES;
    float* logit_out = out + (size_t)N * MODES + (size_t)r * MODES;
#pragma unroll
    for (int q = 0; q < 4; q++) {
        float4 a4, l4;
        float* ap = &a4.x;
        float* lp = &l4.x;
#pragma unroll
        for (int k = 0; k < 4; k++) {
            int i = 4 * q + k;
            ap[k] = ex[i] * inv_s;
            lp[k] = fmaf(-TAU, acc[i] - amin, -lns);
        }
        ((float4*)alpha_out)[q] = a4;
        ((float4*)logit_out)[q] = l4;
    }
}

extern "C" void kernel_launch(void* const* d_in, const int* in_sizes, int n_in,
                              void* d_out, int out_size) {
    const float* V      = (const float*)d_in[0];
    const float* w      = (const float*)d_in[1];
    const float* b      = (const float*)d_in[2];
    const float* gammas = (const float*)d_in[3];
    float* out = (float*)d_out;
    int N = in_sizes[0] / MODES;

    comp_vmin_kernel<<<VMIN_BLOCKS, 256>>>(V, N);
    int blocks = (N + 255) / 256;
    comp_main_kernel<<<blocks, 256>>>(V, w, b, gammas, out, N);
}